// round 2
// baseline (speedup 1.0000x reference)
#include <cuda_runtime.h>

#define BB 4
#define HHH 64
#define LL 4096
#define EE 192
#define NNS 16
#define RR 6
#define KK 4
#define DM 96
#define BL (BB*LL)
#define C152 152

// ------------------------- device scratch (no allocations) ------------------
__device__ float g_xx[BL*EE];
__device__ float g_z [BL*EE];
__device__ float g_xc[BL*EE];
__device__ float g_P [BL*C152];
__device__ float g_delta[16*EE*LL];
__device__ float g_du   [16*EE*LL];
__device__ float g_B2[16*LL*16];
__device__ float g_C2[16*LL*16];
__device__ float g_y [16*EE*LL];
__device__ float g_yt1[BB*EE*LL];
__device__ float g_yt3[BB*EE*LL];
__device__ float g_ym[BL*EE];

__device__ __forceinline__ float ex2f(float x){
    float y; asm("ex2.approx.f32 %0, %1;" : "=f"(y) : "f"(x)); return y;
}
__device__ __forceinline__ float siluf(float x){
    return x / (1.f + __expf(-x));
}
__device__ __forceinline__ float softplusf(float x){
    return fmaxf(x, 0.f) + __logf(1.f + __expf(-fabsf(x)));
}

// ------------------------- tiled GEMM: out[m,n] = sum_k X[m,k]*W[n,k] -------
// MODE 0: X=g_xc -> g_P (Nn=152)
// MODE 1: X=param (x input) -> split g_xx / silu->g_z (Nn=384)
// MODE 2: X=g_ym -> Out (d_out, Nn=96)
template<int KD, int MODE>
__global__ void k_gemm(const float* __restrict__ Xp, const float* __restrict__ W,
                       float* __restrict__ Out, int Nn)
{
    __shared__ float Xs[32][68];
    __shared__ float Ws[32][68];
    const float* __restrict__ X = (MODE==0) ? (const float*)g_xc
                                : (MODE==2) ? (const float*)g_ym : Xp;
    const int m0 = blockIdx.x * 64;
    const int n0 = blockIdx.y * 64;
    const int t  = threadIdx.x;
    const int ty = t >> 4, tx = t & 15;
    float acc[4][4];
    #pragma unroll
    for (int i=0;i<4;i++)
        #pragma unroll
        for (int j=0;j<4;j++) acc[i][j] = 0.f;

    for (int kc = 0; kc < KD/32; kc++){
        __syncthreads();
        #pragma unroll
        for (int idx = t; idx < 64*32; idx += 256){
            int r = idx >> 5, c = idx & 31;
            Xs[c][r] = X[(m0+r)*KD + kc*32 + c];
            int nr = n0 + r;
            Ws[c][r] = (nr < Nn) ? W[nr*KD + kc*32 + c] : 0.f;
        }
        __syncthreads();
        #pragma unroll
        for (int k = 0; k < 32; k++){
            float4 xv = *(const float4*)&Xs[k][ty*4];
            float4 wv = *(const float4*)&Ws[k][tx*4];
            float xr[4] = {xv.x, xv.y, xv.z, xv.w};
            float wr[4] = {wv.x, wv.y, wv.z, wv.w};
            #pragma unroll
            for (int i=0;i<4;i++)
                #pragma unroll
                for (int j=0;j<4;j++) acc[i][j] = fmaf(xr[i], wr[j], acc[i][j]);
        }
    }
    #pragma unroll
    for (int i=0;i<4;i++){
        int m = m0 + ty*4 + i;
        #pragma unroll
        for (int j=0;j<4;j++){
            int n = n0 + tx*4 + j;
            if (MODE == 1){
                if (n < EE) g_xx[m*EE + n] = acc[i][j];
                else        g_z [m*EE + n - EE] = siluf(acc[i][j]);
            } else if (MODE == 0){
                if (n < Nn) g_P[m*C152 + n] = acc[i][j];
            } else {
                if (n < Nn) Out[m*Nn + n] = acc[i][j];
            }
        }
    }
}

// ------------------------- depthwise 3x3 conv + bias + silu -----------------
// grid (4 e-chunks of 48, 64 h, 4 b), block 256
__global__ void k_conv(const float* __restrict__ cw, const float* __restrict__ cb)
{
    __shared__ float xs_s[3][64][48];
    __shared__ float cw_s[48][9];
    const int e0 = blockIdx.x * 48;
    const int h  = blockIdx.y;
    const int b  = blockIdx.z;
    const int t  = threadIdx.x;

    for (int idx = t; idx < 3*64*48; idx += 256){
        int row = idx / (64*48);
        int rem = idx - row*(64*48);
        int w  = rem / 48;
        int ec = rem - w*48;
        int hh = h + row - 1;
        float v = 0.f;
        if (hh >= 0 && hh < HHH)
            v = g_xx[(b*LL + hh*64 + w)*EE + e0 + ec];
        xs_s[row][w][ec] = v;
    }
    for (int idx = t; idx < 48*9; idx += 256){
        int ec = idx / 9, q = idx - ec*9;
        cw_s[ec][q] = cw[(e0+ec)*9 + q];
    }
    __syncthreads();

    for (int o = t; o < 64*48; o += 256){
        int w  = o / 48;
        int ec = o - w*48;
        float acc = cb[e0+ec];
        #pragma unroll
        for (int dh = 0; dh < 3; dh++){
            #pragma unroll
            for (int dw = 0; dw < 3; dw++){
                int ww = w + dw - 1;
                if (ww >= 0 && ww < 64)
                    acc = fmaf(xs_s[dh][ww][ec], cw_s[ec][dh*3+dw], acc);
            }
        }
        g_xc[(b*LL + h*64 + w)*EE + e0 + ec] = siluf(acc);
    }
}

// ------------------------- prep: delta/du + B2/C2 ---------------------------
// grid = B*K*128 (32-l chunks), block 256
__global__ void k_prep(const float* __restrict__ dtw, const float* __restrict__ dtb)
{
    __shared__ float Pt[32][39];
    __shared__ float xr[32][193];
    __shared__ float dtws[EE*RR];
    __shared__ float dtbs[EE];
    __shared__ int   clm[32];
    const int bid = blockIdx.x;
    const int lt = bid & 127;
    const int k  = (bid >> 7) & 3;
    const int b  = bid >> 9;
    const int l0 = lt * 32;
    const int t  = threadIdx.x;

    if (t < 32){
        int l = l0 + t, cl;
        if (k == 0)      cl = l;
        else if (k == 1) cl = (l & 63)*64 + (l >> 6);
        else if (k == 2) cl = (LL-1) - l;
        else { int lp = (LL-1) - l; cl = (lp & 63)*64 + (lp >> 6); }
        clm[t] = cl;
    }
    for (int idx = t; idx < EE*RR; idx += 256) dtws[idx] = dtw[k*EE*RR + idx];
    for (int idx = t; idx < EE;    idx += 256) dtbs[idx] = dtb[k*EE + idx];
    __syncthreads();
    for (int idx = t; idx < 32*38; idx += 256){
        int r = idx / 38, c = idx - r*38;
        Pt[r][c] = g_P[(b*LL + clm[r])*C152 + k*38 + c];
    }
    for (int idx = t; idx < 32*EE; idx += 256){
        int r = idx / EE, d = idx - r*EE;
        xr[r][d] = g_xc[(b*LL + clm[r])*EE + d];
    }
    __syncthreads();

    const int warp = t >> 5, lane = t & 31;
    const int bk = b*KK + k;
    for (int e = warp; e < EE; e += 8){
        float acc = dtbs[e];
        #pragma unroll
        for (int r = 0; r < RR; r++) acc = fmaf(Pt[lane][r], dtws[e*RR + r], acc);
        float dl = softplusf(acc);
        float u  = xr[lane][e];
        int idx = (bk*EE + e)*LL + l0 + lane;
        g_delta[idx] = dl;
        g_du[idx]    = dl * u;
    }
    for (int idx = t; idx < 32*16; idx += 256){
        int pos = idx >> 4, rem = idx & 15;
        int j = rem >> 1, s = rem & 1;
        int o = (bk*LL + l0 + pos)*16 + rem;
        g_B2[o] = Pt[pos][6  + j + 8*s];
        g_C2[o] = Pt[pos][22 + j + 8*s];
    }
}

// ------------------------- selective scan -----------------------------------
// warp = 4 chains (same bk, e0..e0+3); lane: c=lane>>3 chain, j=lane&7 state pair
// grid 192, block 128
__global__ void k_scan(const float* __restrict__ A_logs)
{
    const int W = blockIdx.x*4 + (threadIdx.x >> 5);
    const int lane = threadIdx.x & 31;
    const int bk = W / 48;
    const int e  = (W - bk*48)*4 + (lane >> 3);
    const int j  = lane & 7;
    const int k  = bk & 3;

    const float L2E = 1.4426950408889634f;
    float a0 = -__expf(A_logs[((k*EE + e)*NNS) + j    ]) * L2E;
    float a1 = -__expf(A_logs[((k*EE + e)*NNS) + j + 8]) * L2E;

    const long chb = (long)(bk*EE + e)*LL;
    const float* __restrict__ pd = g_delta + chb;
    const float* __restrict__ pu = g_du    + chb;
    const float* __restrict__ pb = g_B2 + (long)bk*LL*16;
    const float* __restrict__ pc = g_C2 + (long)bk*LL*16;
    float* __restrict__ py = g_y + chb;

    float h0 = 0.f, h1 = 0.f;

    for (int l = 0; l < LL; l += 4){
        float4 d4 = *(const float4*)(pd + l);
        float4 u4 = *(const float4*)(pu + l);
        float dd[4] = {d4.x, d4.y, d4.z, d4.w};
        float uu[4] = {u4.x, u4.y, u4.z, u4.w};
        float ysv = 0.f;
        #pragma unroll
        for (int s = 0; s < 4; s++){
            float2 b2 = *(const float2*)(pb + (l+s)*16 + j*2);
            float2 c2 = *(const float2*)(pc + (l+s)*16 + j*2);
            float dA0 = ex2f(dd[s]*a0);
            float dA1 = ex2f(dd[s]*a1);
            h0 = fmaf(dA0, h0, uu[s]*b2.x);
            h1 = fmaf(dA1, h1, uu[s]*b2.y);
            float p = fmaf(h1, c2.y, h0*c2.x);
            p += __shfl_xor_sync(0xffffffffu, p, 1);
            p += __shfl_xor_sync(0xffffffffu, p, 2);
            p += __shfl_xor_sync(0xffffffffu, p, 4);
            if (j == s) ysv = p;
        }
        if (j < 4) py[l + j] = ysv;
    }
}

// ------------------------- transpose WH directions into canonical -----------
// grid (2,2, B*E*2), block (32,8)
__global__ void k_trans()
{
    __shared__ float s[32][33];
    const int zi = blockIdx.z;
    const int arr = zi & 1;
    const int e = (zi >> 1) % EE;
    const int b = zi / (EE*2);
    const int ti = blockIdx.x, tj = blockIdx.y;
    const int tx = threadIdx.x, ty = threadIdx.y;
    const int kdir = arr ? 3 : 1;
    const float* __restrict__ src = g_y + (long)((b*KK + kdir)*EE + e)*LL;
    float* __restrict__ dst = (arr ? g_yt3 : g_yt1) + (long)(b*EE + e)*LL;

    #pragma unroll
    for (int r = 0; r < 4; r++){
        int w = tj*32 + ty + r*8;
        int h = ti*32 + tx;
        float v;
        if (arr == 0) v = src[w*64 + h];
        else          v = src[(63 - w)*64 + (63 - h)];
        s[ty + r*8][tx] = v;
    }
    __syncthreads();
    #pragma unroll
    for (int r = 0; r < 4; r++){
        int h = ti*32 + ty + r*8;
        int w = tj*32 + tx;
        dst[h*64 + w] = s[tx][ty + r*8];
    }
}

// ------------------------- merge + D*xc + LayerNorm + gate ------------------
// grid (128 l-tiles, 4 b), block 256
__global__ void k_merge(const float* __restrict__ Ds, const float* __restrict__ gamma,
                        const float* __restrict__ beta)
{
    __shared__ float tb[32][193];
    __shared__ float sumD[EE];
    const int l0 = blockIdx.x * 32;
    const int b  = blockIdx.y;
    const int t  = threadIdx.x;

    if (t < EE) sumD[t] = Ds[t] + Ds[EE + t] + Ds[2*EE + t] + Ds[3*EE + t];

    const long y0b = (long)((b*KK + 0)*EE)*LL;
    const long y2b = (long)((b*KK + 2)*EE)*LL;
    const long ytb = (long)(b*EE)*LL;
    for (int idx = t; idx < EE*32; idx += 256){
        int e = idx >> 5, i = idx & 31;
        int l = l0 + i;
        float v = g_y[y0b + (long)e*LL + l]
                + g_y[y2b + (long)e*LL + (LL-1 - l)]
                + g_yt1[ytb + (long)e*LL + l]
                + g_yt3[ytb + (long)e*LL + l];
        tb[i][e] = v;
    }
    __syncthreads();
    for (int idx = t; idx < 32*EE; idx += 256){
        int i = idx / EE, e = idx - i*EE;
        tb[i][e] += sumD[e] * g_xc[(b*LL + l0 + i)*EE + e];
    }
    __syncthreads();

    const int li = t >> 3, ts = t & 7;
    float s1 = 0.f, s2 = 0.f;
    #pragma unroll
    for (int m = 0; m < 24; m++){
        float v = tb[li][ts + 8*m];
        s1 += v; s2 += v*v;
    }
    #pragma unroll
    for (int o = 1; o < 8; o <<= 1){
        s1 += __shfl_xor_sync(0xffffffffu, s1, o);
        s2 += __shfl_xor_sync(0xffffffffu, s2, o);
    }
    const float inv = 1.f / (float)EE;
    float mu = s1 * inv;
    float var = s2 * inv - mu*mu;
    float rstd = rsqrtf(var + 1e-5f);

    const long rowb = (long)(b*LL + l0 + li)*EE;
    #pragma unroll
    for (int m = 0; m < 24; m++){
        int e = ts + 8*m;
        float v = (tb[li][e] - mu) * rstd * gamma[e] + beta[e];
        g_ym[rowb + e] = v * g_z[rowb + e];
    }
}

// ------------------------- launcher -----------------------------------------
extern "C" void kernel_launch(void* const* d_in, const int* in_sizes, int n_in,
                              void* d_out, int out_size)
{
    const float* x    = (const float*)d_in[0];
    const float* ipw  = (const float*)d_in[1];
    const float* cw   = (const float*)d_in[2];
    const float* cb   = (const float*)d_in[3];
    const float* xpw  = (const float*)d_in[4];
    const float* dtw  = (const float*)d_in[5];
    const float* dtb  = (const float*)d_in[6];
    const float* alog = (const float*)d_in[7];
    const float* Ds   = (const float*)d_in[8];
    const float* lng  = (const float*)d_in[9];
    const float* lnb  = (const float*)d_in[10];
    const float* opw  = (const float*)d_in[11];
    float* out = (float*)d_out;

    k_gemm<DM, 1><<<dim3(BL/64, 6), 256>>>(x, ipw, nullptr, 2*EE);
    k_conv<<<dim3(4, 64, BB), 256>>>(cw, cb);
    k_gemm<EE, 0><<<dim3(BL/64, 3), 256>>>(nullptr, xpw, nullptr, C152);
    k_prep<<<BB*KK*128, 256>>>(dtw, dtb);
    k_scan<<<192, 128>>>(alog);
    k_trans<<<dim3(2, 2, BB*EE*2), dim3(32, 8)>>>();
    k_merge<<<dim3(128, BB), 256>>>(Ds, lng, lnb);
    k_gemm<EE, 2><<<dim3(BL/64, 2), 256>>>(nullptr, opw, out, DM);
}

// round 3
// speedup vs baseline: 2.8670x; 2.8670x over previous
#include <cuda_runtime.h>

#define BB 4
#define HHH 64
#define LL 4096
#define EE 192
#define NNS 16
#define RR 6
#define KK 4
#define DM 96
#define BL (BB*LL)
#define C152 152
#define NCH 8
#define CHL 512   // LL/NCH

// ------------------------- device scratch (no allocations) ------------------
__device__ float g_xx[BL*EE];
__device__ float g_z [BL*EE];
__device__ float g_xc[BL*EE];
__device__ float g_P [BL*C152];
__device__ float g_delta[16*EE*LL];
__device__ float g_du   [16*EE*LL];
__device__ float g_B2[16*LL*16];
__device__ float g_C2[16*LL*16];
__device__ float g_y [16*EE*LL];
__device__ float g_yt1[BB*EE*LL];
__device__ float g_yt3[BB*EE*LL];
__device__ float g_ym[BL*EE];
// chunked-scan carries: chain = bk*EE+e in [0,3072)
__device__ float g_hfin[3072*NCH*16];
__device__ float g_hin [3072*NCH*16];
__device__ float g_Sdd [3072*NCH];

__device__ __forceinline__ float ex2f(float x){
    float y; asm("ex2.approx.f32 %0, %1;" : "=f"(y) : "f"(x)); return y;
}
__device__ __forceinline__ float siluf(float x){
    return x / (1.f + __expf(-x));
}
__device__ __forceinline__ float softplusf(float x){
    return fmaxf(x, 0.f) + __logf(1.f + __expf(-fabsf(x)));
}

// ------------------------- tiled GEMM: out[m,n] = sum_k X[m,k]*W[n,k] -------
// 128x64 tile, 256 threads, 8x4 micro-tile
// MODE 0: X=g_xc -> g_P (Nn=152)
// MODE 1: X=param (x input) -> split g_xx / silu->g_z (Nn=384)
// MODE 2: X=g_ym -> Out (d_out, Nn=96)
template<int KD, int MODE>
__global__ void k_gemm(const float* __restrict__ Xp, const float* __restrict__ W,
                       float* __restrict__ Out, int Nn)
{
    __shared__ float Xs[32][132];
    __shared__ float Ws[32][68];
    const float* __restrict__ X = (MODE==0) ? (const float*)g_xc
                                : (MODE==2) ? (const float*)g_ym : Xp;
    const int m0 = blockIdx.x * 128;
    const int n0 = blockIdx.y * 64;
    const int t  = threadIdx.x;
    const int ty = t >> 4, tx = t & 15;
    float acc[8][4];
    #pragma unroll
    for (int i=0;i<8;i++)
        #pragma unroll
        for (int j=0;j<4;j++) acc[i][j] = 0.f;

    const int lc4 = (t & 7) * 4;
    const int lr0 = t >> 3;

    for (int kc = 0; kc < KD/32; kc++){
        __syncthreads();
        #pragma unroll
        for (int i = 0; i < 4; i++){
            int r = lr0 + 32*i;
            float4 v = *(const float4*)&X[(m0+r)*KD + kc*32 + lc4];
            Xs[lc4+0][r] = v.x; Xs[lc4+1][r] = v.y;
            Xs[lc4+2][r] = v.z; Xs[lc4+3][r] = v.w;
        }
        #pragma unroll
        for (int i = 0; i < 2; i++){
            int r = lr0 + 32*i;
            int nr = n0 + r;
            float4 v = make_float4(0.f,0.f,0.f,0.f);
            if (nr < Nn) v = *(const float4*)&W[nr*KD + kc*32 + lc4];
            Ws[lc4+0][r] = v.x; Ws[lc4+1][r] = v.y;
            Ws[lc4+2][r] = v.z; Ws[lc4+3][r] = v.w;
        }
        __syncthreads();
        #pragma unroll
        for (int k = 0; k < 32; k++){
            float4 x0 = *(const float4*)&Xs[k][ty*8];
            float4 x1 = *(const float4*)&Xs[k][ty*8+4];
            float4 wv = *(const float4*)&Ws[k][tx*4];
            float xr[8] = {x0.x,x0.y,x0.z,x0.w,x1.x,x1.y,x1.z,x1.w};
            float wr[4] = {wv.x,wv.y,wv.z,wv.w};
            #pragma unroll
            for (int i=0;i<8;i++)
                #pragma unroll
                for (int j=0;j<4;j++) acc[i][j] = fmaf(xr[i], wr[j], acc[i][j]);
        }
    }
    #pragma unroll
    for (int i=0;i<8;i++){
        int m = m0 + ty*8 + i;
        #pragma unroll
        for (int j=0;j<4;j++){
            int n = n0 + tx*4 + j;
            if (MODE == 1){
                if (n < EE) g_xx[m*EE + n] = acc[i][j];
                else        g_z [m*EE + n - EE] = siluf(acc[i][j]);
            } else if (MODE == 0){
                if (n < Nn) g_P[m*C152 + n] = acc[i][j];
            } else {
                if (n < Nn) Out[m*Nn + n] = acc[i][j];
            }
        }
    }
}

// ------------------------- depthwise 3x3 conv + bias + silu -----------------
__global__ void k_conv(const float* __restrict__ cw, const float* __restrict__ cb)
{
    __shared__ float xs_s[3][64][48];
    __shared__ float cw_s[48][9];
    const int e0 = blockIdx.x * 48;
    const int h  = blockIdx.y;
    const int b  = blockIdx.z;
    const int t  = threadIdx.x;

    for (int idx = t; idx < 3*64*48; idx += 256){
        int row = idx / (64*48);
        int rem = idx - row*(64*48);
        int w  = rem / 48;
        int ec = rem - w*48;
        int hh = h + row - 1;
        float v = 0.f;
        if (hh >= 0 && hh < HHH)
            v = g_xx[(b*LL + hh*64 + w)*EE + e0 + ec];
        xs_s[row][w][ec] = v;
    }
    for (int idx = t; idx < 48*9; idx += 256){
        int ec = idx / 9, q = idx - ec*9;
        cw_s[ec][q] = cw[(e0+ec)*9 + q];
    }
    __syncthreads();

    for (int o = t; o < 64*48; o += 256){
        int w  = o / 48;
        int ec = o - w*48;
        float acc = cb[e0+ec];
        #pragma unroll
        for (int dh = 0; dh < 3; dh++){
            #pragma unroll
            for (int dw = 0; dw < 3; dw++){
                int ww = w + dw - 1;
                if (ww >= 0 && ww < 64)
                    acc = fmaf(xs_s[dh][ww][ec], cw_s[ec][dh*3+dw], acc);
            }
        }
        g_xc[(b*LL + h*64 + w)*EE + e0 + ec] = siluf(acc);
    }
}

// ------------------------- prep: delta/du + B2/C2 ---------------------------
__global__ void k_prep(const float* __restrict__ dtw, const float* __restrict__ dtb)
{
    __shared__ float Pt[32][39];
    __shared__ float xr[32][193];
    __shared__ float dtws[EE*RR];
    __shared__ float dtbs[EE];
    __shared__ int   clm[32];
    const int bid = blockIdx.x;
    const int lt = bid & 127;
    const int k  = (bid >> 7) & 3;
    const int b  = bid >> 9;
    const int l0 = lt * 32;
    const int t  = threadIdx.x;

    if (t < 32){
        int l = l0 + t, cl;
        if (k == 0)      cl = l;
        else if (k == 1) cl = (l & 63)*64 + (l >> 6);
        else if (k == 2) cl = (LL-1) - l;
        else { int lp = (LL-1) - l; cl = (lp & 63)*64 + (lp >> 6); }
        clm[t] = cl;
    }
    for (int idx = t; idx < EE*RR; idx += 256) dtws[idx] = dtw[k*EE*RR + idx];
    for (int idx = t; idx < EE;    idx += 256) dtbs[idx] = dtb[k*EE + idx];
    __syncthreads();
    for (int idx = t; idx < 32*38; idx += 256){
        int r = idx / 38, c = idx - r*38;
        Pt[r][c] = g_P[(b*LL + clm[r])*C152 + k*38 + c];
    }
    for (int idx = t; idx < 32*EE; idx += 256){
        int r = idx / EE, d = idx - r*EE;
        xr[r][d] = g_xc[(b*LL + clm[r])*EE + d];
    }
    __syncthreads();

    const int warp = t >> 5, lane = t & 31;
    const int bk = b*KK + k;
    for (int e = warp; e < EE; e += 8){
        float acc = dtbs[e];
        #pragma unroll
        for (int r = 0; r < RR; r++) acc = fmaf(Pt[lane][r], dtws[e*RR + r], acc);
        float dl = softplusf(acc);
        float u  = xr[lane][e];
        int idx = (bk*EE + e)*LL + l0 + lane;
        g_delta[idx] = dl;
        g_du[idx]    = dl * u;
    }
    for (int idx = t; idx < 32*16; idx += 256){
        int pos = idx >> 4, rem = idx & 15;
        int j = rem >> 1, s = rem & 1;
        int o = (bk*LL + l0 + pos)*16 + rem;
        g_B2[o] = Pt[pos][6  + j + 8*s];
        g_C2[o] = Pt[pos][22 + j + 8*s];
    }
}

// ------------------------- scan pass 1: per-chunk local (h_fin, Sdd) --------
// warp = 4 chains x chunk; chunks 0..6 only. grid 672 blocks x 8 warps.
__global__ void k_scan1(const float* __restrict__ A_logs)
{
    const int W = blockIdx.x*8 + (threadIdx.x >> 5);   // [0, 5376)
    const int lane = threadIdx.x & 31;
    const int cidx  = W / 7;          // chain group [0,768)
    const int chunk = W - cidx*7;     // [0,7)
    const int bk = cidx / 48;
    const int e  = (cidx - bk*48)*4 + (lane >> 3);
    const int j  = lane & 7;
    const int k  = bk & 3;

    const float L2E = 1.4426950408889634f;
    float a0 = -__expf(A_logs[(k*EE + e)*NNS + j    ]) * L2E;
    float a1 = -__expf(A_logs[(k*EE + e)*NNS + j + 8]) * L2E;

    const int ch = bk*EE + e;
    const long chb = (long)ch*LL;
    const float* __restrict__ pd = g_delta + chb;
    const float* __restrict__ pu = g_du    + chb;
    const float* __restrict__ pb = g_B2 + (long)bk*LL*16;

    float h0 = 0.f, h1 = 0.f, sdd = 0.f;
    const int l0 = chunk*CHL;

    for (int l = l0; l < l0 + CHL; l += 4){
        float4 d4 = *(const float4*)(pd + l);
        float4 u4 = *(const float4*)(pu + l);
        float dd[4] = {d4.x, d4.y, d4.z, d4.w};
        float uu[4] = {u4.x, u4.y, u4.z, u4.w};
        #pragma unroll
        for (int s = 0; s < 4; s++){
            float2 b2 = *(const float2*)(pb + (l+s)*16 + j*2);
            float dA0 = ex2f(dd[s]*a0);
            float dA1 = ex2f(dd[s]*a1);
            h0 = fmaf(dA0, h0, uu[s]*b2.x);
            h1 = fmaf(dA1, h1, uu[s]*b2.y);
        }
        sdd += dd[0] + dd[1] + dd[2] + dd[3];
    }
    int hb = ((ch*NCH + chunk)*8 + j)*2;
    *(float2*)&g_hfin[hb] = make_float2(h0, h1);
    if (j == 0) g_Sdd[ch*NCH + chunk] = sdd;
}

// ------------------------- scan mid: carry propagation ----------------------
// thread = (chain, j). grid 96 x 256.
__global__ void k_scanmid(const float* __restrict__ A_logs)
{
    const int tid = blockIdx.x*256 + threadIdx.x;   // [0, 24576)
    const int ch = tid >> 3;
    const int j  = tid & 7;
    const int e  = ch % EE;
    const int k  = (ch / EE) & 3;
    float a0 = -__expf(A_logs[(k*EE + e)*NNS + j    ]);
    float a1 = -__expf(A_logs[(k*EE + e)*NNS + j + 8]);

    float h0 = 0.f, h1 = 0.f;
    #pragma unroll
    for (int c = 0; c < NCH; c++){
        *(float2*)&g_hin[((ch*NCH + c)*8 + j)*2] = make_float2(h0, h1);
        if (c < NCH-1){
            float2 hf = *(const float2*)&g_hfin[((ch*NCH + c)*8 + j)*2];
            float S = g_Sdd[ch*NCH + c];
            h0 = hf.x + __expf(a0*S)*h0;
            h1 = hf.y + __expf(a1*S)*h1;
        }
    }
}

// ------------------------- scan pass 2: full scan with y --------------------
// warp = 4 chains x chunk; all 8 chunks. grid 768 blocks x 8 warps.
__global__ void k_scan2(const float* __restrict__ A_logs)
{
    const int W = blockIdx.x*8 + (threadIdx.x >> 5);   // [0, 6144)
    const int lane = threadIdx.x & 31;
    const int cidx  = W >> 3;
    const int chunk = W & 7;
    const int bk = cidx / 48;
    const int e  = (cidx - bk*48)*4 + (lane >> 3);
    const int j  = lane & 7;
    const int k  = bk & 3;

    const float L2E = 1.4426950408889634f;
    float a0 = -__expf(A_logs[(k*EE + e)*NNS + j    ]) * L2E;
    float a1 = -__expf(A_logs[(k*EE + e)*NNS + j + 8]) * L2E;

    const int ch = bk*EE + e;
    const long chb = (long)ch*LL;
    const float* __restrict__ pd = g_delta + chb;
    const float* __restrict__ pu = g_du    + chb;
    const float* __restrict__ pb = g_B2 + (long)bk*LL*16;
    const float* __restrict__ pc = g_C2 + (long)bk*LL*16;
    float* __restrict__ py = g_y + chb;

    float2 h00 = *(const float2*)&g_hin[((ch*NCH + chunk)*8 + j)*2];
    float h0 = h00.x, h1 = h00.y;
    const int l0 = chunk*CHL;

    for (int l = l0; l < l0 + CHL; l += 4){
        float4 d4 = *(const float4*)(pd + l);
        float4 u4 = *(const float4*)(pu + l);
        float dd[4] = {d4.x, d4.y, d4.z, d4.w};
        float uu[4] = {u4.x, u4.y, u4.z, u4.w};
        float ysv = 0.f;
        #pragma unroll
        for (int s = 0; s < 4; s++){
            float2 b2 = *(const float2*)(pb + (l+s)*16 + j*2);
            float2 c2 = *(const float2*)(pc + (l+s)*16 + j*2);
            float dA0 = ex2f(dd[s]*a0);
            float dA1 = ex2f(dd[s]*a1);
            h0 = fmaf(dA0, h0, uu[s]*b2.x);
            h1 = fmaf(dA1, h1, uu[s]*b2.y);
            float p = fmaf(h1, c2.y, h0*c2.x);
            p += __shfl_xor_sync(0xffffffffu, p, 1);
            p += __shfl_xor_sync(0xffffffffu, p, 2);
            p += __shfl_xor_sync(0xffffffffu, p, 4);
            if (j == s) ysv = p;
        }
        if (j < 4) py[l + j] = ysv;
    }
}

// ------------------------- transpose WH directions into canonical -----------
__global__ void k_trans()
{
    __shared__ float s[32][33];
    const int zi = blockIdx.z;
    const int arr = zi & 1;
    const int e = (zi >> 1) % EE;
    const int b = zi / (EE*2);
    const int ti = blockIdx.x, tj = blockIdx.y;
    const int tx = threadIdx.x, ty = threadIdx.y;
    const int kdir = arr ? 3 : 1;
    const float* __restrict__ src = g_y + (long)((b*KK + kdir)*EE + e)*LL;
    float* __restrict__ dst = (arr ? g_yt3 : g_yt1) + (long)(b*EE + e)*LL;

    #pragma unroll
    for (int r = 0; r < 4; r++){
        int w = tj*32 + ty + r*8;
        int h = ti*32 + tx;
        float v;
        if (arr == 0) v = src[w*64 + h];
        else          v = src[(63 - w)*64 + (63 - h)];
        s[ty + r*8][tx] = v;
    }
    __syncthreads();
    #pragma unroll
    for (int r = 0; r < 4; r++){
        int h = ti*32 + ty + r*8;
        int w = tj*32 + tx;
        dst[h*64 + w] = s[tx][ty + r*8];
    }
}

// ------------------------- merge + D*xc + LayerNorm + gate ------------------
__global__ void k_merge(const float* __restrict__ Ds, const float* __restrict__ gamma,
                        const float* __restrict__ beta)
{
    __shared__ float tb[32][193];
    __shared__ float sumD[EE];
    const int l0 = blockIdx.x * 32;
    const int b  = blockIdx.y;
    const int t  = threadIdx.x;

    if (t < EE) sumD[t] = Ds[t] + Ds[EE + t] + Ds[2*EE + t] + Ds[3*EE + t];

    const long y0b = (long)((b*KK + 0)*EE)*LL;
    const long y2b = (long)((b*KK + 2)*EE)*LL;
    const long ytb = (long)(b*EE)*LL;
    for (int idx = t; idx < EE*32; idx += 256){
        int e = idx >> 5, i = idx & 31;
        int l = l0 + i;
        float v = g_y[y0b + (long)e*LL + l]
                + g_y[y2b + (long)e*LL + (LL-1 - l)]
                + g_yt1[ytb + (long)e*LL + l]
                + g_yt3[ytb + (long)e*LL + l];
        tb[i][e] = v;
    }
    __syncthreads();
    for (int idx = t; idx < 32*EE; idx += 256){
        int i = idx / EE, e = idx - i*EE;
        tb[i][e] += sumD[e] * g_xc[(b*LL + l0 + i)*EE + e];
    }
    __syncthreads();

    const int li = t >> 3, ts = t & 7;
    float s1 = 0.f, s2 = 0.f;
    #pragma unroll
    for (int m = 0; m < 24; m++){
        float v = tb[li][ts + 8*m];
        s1 += v; s2 += v*v;
    }
    #pragma unroll
    for (int o = 1; o < 8; o <<= 1){
        s1 += __shfl_xor_sync(0xffffffffu, s1, o);
        s2 += __shfl_xor_sync(0xffffffffu, s2, o);
    }
    const float inv = 1.f / (float)EE;
    float mu = s1 * inv;
    float var = s2 * inv - mu*mu;
    float rstd = rsqrtf(var + 1e-5f);

    const long rowb = (long)(b*LL + l0 + li)*EE;
    #pragma unroll
    for (int m = 0; m < 24; m++){
        int e = ts + 8*m;
        float v = (tb[li][e] - mu) * rstd * gamma[e] + beta[e];
        g_ym[rowb + e] = v * g_z[rowb + e];
    }
}

// ------------------------- launcher -----------------------------------------
extern "C" void kernel_launch(void* const* d_in, const int* in_sizes, int n_in,
                              void* d_out, int out_size)
{
    const float* x    = (const float*)d_in[0];
    const float* ipw  = (const float*)d_in[1];
    const float* cw   = (const float*)d_in[2];
    const float* cb   = (const float*)d_in[3];
    const float* xpw  = (const float*)d_in[4];
    const float* dtw  = (const float*)d_in[5];
    const float* dtb  = (const float*)d_in[6];
    const float* alog = (const float*)d_in[7];
    const float* Ds   = (const float*)d_in[8];
    const float* lng  = (const float*)d_in[9];
    const float* lnb  = (const float*)d_in[10];
    const float* opw  = (const float*)d_in[11];
    float* out = (float*)d_out;

    k_gemm<DM, 1><<<dim3(128, 6), 256>>>(x, ipw, nullptr, 2*EE);
    k_conv<<<dim3(4, 64, BB), 256>>>(cw, cb);
    k_gemm<EE, 0><<<dim3(128, 3), 256>>>(nullptr, xpw, nullptr, C152);
    k_prep<<<BB*KK*128, 256>>>(dtw, dtb);
    k_scan1<<<672, 256>>>(alog);
    k_scanmid<<<96, 256>>>(alog);
    k_scan2<<<768, 256>>>(alog);
    k_trans<<<dim3(2, 2, BB*EE*2), dim3(32, 8)>>>();
    k_merge<<<dim3(128, BB), 256>>>(Ds, lng, lnb);
    k_gemm<EE, 2><<<dim3(128, 2), 256>>>(nullptr, opw, out, DM);
}

// round 4
// speedup vs baseline: 3.8110x; 1.3292x over previous
#include <cuda_runtime.h>

#define BB 4
#define HHH 64
#define LL 4096
#define EE 192
#define NNS 16
#define RR 6
#define KK 4
#define DM 96
#define BL (BB*LL)
#define C152 152
#define NCH 8
#define CHL 512   // LL/NCH

typedef unsigned long long u64;

// ------------------------- device scratch (no allocations) ------------------
__device__ float g_xx[BL*EE];
__device__ float g_z [BL*EE];
__device__ float g_xc[BL*EE];
__device__ float g_P [BL*C152];
__device__ float g_delta[16*EE*LL];
__device__ float g_du   [16*EE*LL];
__device__ float g_B4[16*LL*16];
__device__ float g_C4[16*LL*16];
__device__ float g_y [16*EE*LL];
__device__ float g_yt1[BB*EE*LL];
__device__ float g_yt3[BB*EE*LL];
__device__ float g_ym[BL*EE];
// chunked-scan carries: chain = bk*EE+e in [0,3072); state slot np = lj*4+s
__device__ float g_hfin[3072*NCH*16];
__device__ float g_hin [3072*NCH*16];
__device__ float g_Sdd [3072*NCH];

__device__ __forceinline__ float ex2f(float x){
    float y; asm("ex2.approx.f32 %0, %1;" : "=f"(y) : "f"(x)); return y;
}
__device__ __forceinline__ float siluf(float x){
    return x / (1.f + __expf(-x));
}
__device__ __forceinline__ float softplusf(float x){
    return fmaxf(x, 0.f) + __logf(1.f + __expf(-fabsf(x)));
}
__device__ __forceinline__ u64 fma2(u64 a, u64 b, u64 c){
    u64 d; asm("fma.rn.f32x2 %0, %1, %2, %3;" : "=l"(d) : "l"(a), "l"(b), "l"(c));
    return d;
}
__device__ __forceinline__ u64 pack2(float x, float y){
    u64 d; asm("mov.b64 %0, {%1, %2};" : "=l"(d) : "f"(x), "f"(y));
    return d;
}
__device__ __forceinline__ void unpack2(u64 v, float& lo, float& hi){
    asm("mov.b64 {%0, %1}, %2;" : "=f"(lo), "=f"(hi) : "l"(v));
}

// ------------------------- tiled GEMM: out[m,n] = sum_k X[m,k]*W[n,k] -------
// 128x64 tile, 256 threads, 8x4 micro-tile, f32x2 packed accumulation
// MODE 0: X=g_xc -> g_P (Nn=152)
// MODE 1: X=param (x input) -> split g_xx / silu->g_z (Nn=384)
// MODE 2: X=g_ym -> Out (d_out, Nn=96)
template<int KD, int MODE>
__global__ void __launch_bounds__(256)
k_gemm(const float* __restrict__ Xp, const float* __restrict__ W,
       float* __restrict__ Out, int Nn)
{
    __shared__ float Xs[32][132];
    __shared__ float Ws[32][68];
    const float* __restrict__ X = (MODE==0) ? (const float*)g_xc
                                : (MODE==2) ? (const float*)g_ym : Xp;
    const int m0 = blockIdx.x * 128;
    const int n0 = blockIdx.y * 64;
    const int t  = threadIdx.x;
    const int ty = t >> 4, tx = t & 15;
    u64 acc2[4][4];
    #pragma unroll
    for (int i=0;i<4;i++)
        #pragma unroll
        for (int j=0;j<4;j++) acc2[i][j] = 0ull;

    const int lc4 = (t & 7) * 4;
    const int lr0 = t >> 3;

    for (int kc = 0; kc < KD/32; kc++){
        __syncthreads();
        #pragma unroll
        for (int i = 0; i < 4; i++){
            int r = lr0 + 32*i;
            float4 v = *(const float4*)&X[(m0+r)*KD + kc*32 + lc4];
            Xs[lc4+0][r] = v.x; Xs[lc4+1][r] = v.y;
            Xs[lc4+2][r] = v.z; Xs[lc4+3][r] = v.w;
        }
        #pragma unroll
        for (int i = 0; i < 2; i++){
            int r = lr0 + 32*i;
            int nr = n0 + r;
            float4 v = make_float4(0.f,0.f,0.f,0.f);
            if (nr < Nn) v = *(const float4*)&W[nr*KD + kc*32 + lc4];
            Ws[lc4+0][r] = v.x; Ws[lc4+1][r] = v.y;
            Ws[lc4+2][r] = v.z; Ws[lc4+3][r] = v.w;
        }
        __syncthreads();
        #pragma unroll
        for (int k = 0; k < 32; k++){
            const u64* xp = (const u64*)&Xs[k][ty*8];
            u64 x2[4] = {xp[0], xp[1], xp[2], xp[3]};
            float4 wv = *(const float4*)&Ws[k][tx*4];
            u64 w2[4] = {pack2(wv.x,wv.x), pack2(wv.y,wv.y),
                         pack2(wv.z,wv.z), pack2(wv.w,wv.w)};
            #pragma unroll
            for (int i=0;i<4;i++)
                #pragma unroll
                for (int j=0;j<4;j++) acc2[i][j] = fma2(x2[i], w2[j], acc2[i][j]);
        }
    }
    #pragma unroll
    for (int i=0;i<4;i++){
        #pragma unroll
        for (int j=0;j<4;j++){
            float lo, hi;
            unpack2(acc2[i][j], lo, hi);
            int n = n0 + tx*4 + j;
            int mA = m0 + ty*8 + 2*i;
            #pragma unroll
            for (int pp = 0; pp < 2; pp++){
                int m = mA + pp;
                float v = pp ? hi : lo;
                if (MODE == 1){
                    if (n < EE) g_xx[m*EE + n] = v;
                    else        g_z [m*EE + n - EE] = siluf(v);
                } else if (MODE == 0){
                    if (n < Nn) g_P[m*C152 + n] = v;
                } else {
                    if (n < Nn) Out[m*Nn + n] = v;
                }
            }
        }
    }
}

// ------------------------- depthwise 3x3 conv + bias + silu -----------------
__global__ void __launch_bounds__(256) k_conv(const float* __restrict__ cw, const float* __restrict__ cb)
{
    __shared__ float xs_s[3][64][48];
    __shared__ float cw_s[48][9];
    const int e0 = blockIdx.x * 48;
    const int h  = blockIdx.y;
    const int b  = blockIdx.z;
    const int t  = threadIdx.x;

    for (int idx = t; idx < 3*64*48; idx += 256){
        int row = idx / (64*48);
        int rem = idx - row*(64*48);
        int w  = rem / 48;
        int ec = rem - w*48;
        int hh = h + row - 1;
        float v = 0.f;
        if (hh >= 0 && hh < HHH)
            v = g_xx[(b*LL + hh*64 + w)*EE + e0 + ec];
        xs_s[row][w][ec] = v;
    }
    for (int idx = t; idx < 48*9; idx += 256){
        int ec = idx / 9, q = idx - ec*9;
        cw_s[ec][q] = cw[(e0+ec)*9 + q];
    }
    __syncthreads();

    for (int o = t; o < 64*48; o += 256){
        int w  = o / 48;
        int ec = o - w*48;
        float acc = cb[e0+ec];
        #pragma unroll
        for (int dh = 0; dh < 3; dh++){
            #pragma unroll
            for (int dw = 0; dw < 3; dw++){
                int ww = w + dw - 1;
                if (ww >= 0 && ww < 64)
                    acc = fmaf(xs_s[dh][ww][ec], cw_s[ec][dh*3+dw], acc);
            }
        }
        g_xc[(b*LL + h*64 + w)*EE + e0 + ec] = siluf(acc);
    }
}

// ------------------------- prep: delta/du + B4/C4 ---------------------------
// B4/C4 slot layout per l: np = lj*4 + s  <->  state n = 4*s + lj
__global__ void __launch_bounds__(256) k_prep(const float* __restrict__ dtw, const float* __restrict__ dtb)
{
    __shared__ float Pt[32][39];
    __shared__ float xr[32][193];
    __shared__ float dtws[EE*RR];
    __shared__ float dtbs[EE];
    __shared__ int   clm[32];
    const int bid = blockIdx.x;
    const int lt = bid & 127;
    const int k  = (bid >> 7) & 3;
    const int b  = bid >> 9;
    const int l0 = lt * 32;
    const int t  = threadIdx.x;

    if (t < 32){
        int l = l0 + t, cl;
        if (k == 0)      cl = l;
        else if (k == 1) cl = (l & 63)*64 + (l >> 6);
        else if (k == 2) cl = (LL-1) - l;
        else { int lp = (LL-1) - l; cl = (lp & 63)*64 + (lp >> 6); }
        clm[t] = cl;
    }
    for (int idx = t; idx < EE*RR; idx += 256) dtws[idx] = dtw[k*EE*RR + idx];
    for (int idx = t; idx < EE;    idx += 256) dtbs[idx] = dtb[k*EE + idx];
    __syncthreads();
    for (int idx = t; idx < 32*38; idx += 256){
        int r = idx / 38, c = idx - r*38;
        Pt[r][c] = g_P[(b*LL + clm[r])*C152 + k*38 + c];
    }
    for (int idx = t; idx < 32*48; idx += 256){
        int r = idx / 48, c = idx - r*48;
        float4 v = *(const float4*)&g_xc[(b*LL + clm[r])*EE + c*4];
        xr[r][c*4+0] = v.x; xr[r][c*4+1] = v.y;
        xr[r][c*4+2] = v.z; xr[r][c*4+3] = v.w;
    }
    __syncthreads();

    const int warp = t >> 5, lane = t & 31;
    const int bk = b*KK + k;
    for (int e = warp; e < EE; e += 8){
        float acc = dtbs[e];
        #pragma unroll
        for (int r = 0; r < RR; r++) acc = fmaf(Pt[lane][r], dtws[e*RR + r], acc);
        float dl = softplusf(acc);
        float u  = xr[lane][e];
        int idx = (bk*EE + e)*LL + l0 + lane;
        g_delta[idx] = dl;
        g_du[idx]    = dl * u;
    }
    for (int idx = t; idx < 32*16; idx += 256){
        int pos = idx >> 4, np = idx & 15;
        int n = 4*(np & 3) + (np >> 2);     // state index for slot np
        int o = (bk*LL + l0 + pos)*16 + np;
        g_B4[o] = Pt[pos][6  + n];
        g_C4[o] = Pt[pos][22 + n];
    }
}

// ------------------------- scan pass 1: per-chunk local (h_fin, Sdd) --------
// warp = 8 chains (same bk, consecutive e); 4 lanes/chain, 4 states/lane.
// chunks 0..6 only. grid 336 blocks x 8 warps = 2688 warps.
__global__ void __launch_bounds__(256) k_scan1(const float* __restrict__ A_logs)
{
    const int W = blockIdx.x*8 + (threadIdx.x >> 5);   // [0, 2688)
    const int lane = threadIdx.x & 31;
    const int cidx  = W / 7;          // chain group [0,384)
    const int chunk = W - cidx*7;     // [0,7)
    const int bk = cidx / 24;
    const int e  = (cidx - bk*24)*8 + (lane >> 2);
    const int lj = lane & 3;
    const int k  = bk & 3;

    const float L2E = 1.4426950408889634f;
    float am[4]; bool okl = true;
    #pragma unroll
    for (int s = 0; s < 4; s++){
        int n = 4*s + lj;
        float av = -__expf(A_logs[(k*EE + e)*NNS + n]);
        am[s] = av * L2E;
        okl &= fabsf(av + (float)(n+1)) < 1e-4f * (float)(n+1);
    }
    const bool ok = __all_sync(0xffffffffu, okl);

    const int ch = bk*EE + e;
    const long chb = (long)ch*LL;
    const float* __restrict__ pd = g_delta + chb;
    const float* __restrict__ pu = g_du    + chb;
    const float* __restrict__ pb = g_B4 + (long)bk*LL*16;

    float h0=0.f, h1=0.f, h2=0.f, h3=0.f, sdd = 0.f;
    const int l0 = chunk*CHL;
    const float am0 = am[0];

    if (ok){
        for (int l = l0; l < l0 + CHL; l += 4){
            float4 d4 = *(const float4*)(pd + l);
            float4 u4 = *(const float4*)(pu + l);
            float dd[4] = {d4.x, d4.y, d4.z, d4.w};
            float uu[4] = {u4.x, u4.y, u4.z, u4.w};
            #pragma unroll
            for (int s = 0; s < 4; s++){
                float4 b4 = *(const float4*)(pb + (l+s)*16 + lj*4);
                float t  = ex2f(dd[s]*am0);
                float q4 = __shfl_sync(0xffffffffu, t, 3, 4);
                float dA1 = t*q4, dA2 = dA1*q4, dA3 = dA2*q4;
                float us = uu[s];
                h0 = fmaf(t,   h0, us*b4.x);
                h1 = fmaf(dA1, h1, us*b4.y);
                h2 = fmaf(dA2, h2, us*b4.z);
                h3 = fmaf(dA3, h3, us*b4.w);
            }
            sdd += dd[0] + dd[1] + dd[2] + dd[3];
        }
    } else {
        for (int l = l0; l < l0 + CHL; l += 4){
            float4 d4 = *(const float4*)(pd + l);
            float4 u4 = *(const float4*)(pu + l);
            float dd[4] = {d4.x, d4.y, d4.z, d4.w};
            float uu[4] = {u4.x, u4.y, u4.z, u4.w};
            #pragma unroll
            for (int s = 0; s < 4; s++){
                float4 b4 = *(const float4*)(pb + (l+s)*16 + lj*4);
                float us = uu[s];
                h0 = fmaf(ex2f(dd[s]*am[0]), h0, us*b4.x);
                h1 = fmaf(ex2f(dd[s]*am[1]), h1, us*b4.y);
                h2 = fmaf(ex2f(dd[s]*am[2]), h2, us*b4.z);
                h3 = fmaf(ex2f(dd[s]*am[3]), h3, us*b4.w);
            }
            sdd += dd[0] + dd[1] + dd[2] + dd[3];
        }
    }
    int hb = (ch*NCH + chunk)*16 + lj*4;
    *(float4*)&g_hfin[hb] = make_float4(h0, h1, h2, h3);
    if (lj == 0) g_Sdd[ch*NCH + chunk] = sdd;
}

// ------------------------- scan mid: carry propagation ----------------------
// thread = (chain, np). grid 192 x 256.
__global__ void __launch_bounds__(256) k_scanmid(const float* __restrict__ A_logs)
{
    const int tid = blockIdx.x*256 + threadIdx.x;   // [0, 49152)
    const int ch = tid >> 4;
    const int np = tid & 15;
    const int n  = 4*(np & 3) + (np >> 2);
    const int e  = ch % EE;
    const int k  = (ch / EE) & 3;
    float a = -__expf(A_logs[(k*EE + e)*NNS + n]);

    float h = 0.f;
    #pragma unroll
    for (int c = 0; c < NCH; c++){
        g_hin[(ch*NCH + c)*16 + np] = h;
        if (c < NCH-1){
            float hf = g_hfin[(ch*NCH + c)*16 + np];
            float S = g_Sdd[ch*NCH + c];
            h = hf + __expf(a*S)*h;
        }
    }
}

// ------------------------- scan pass 2: full scan with y --------------------
// all 8 chunks. grid 384 blocks x 8 warps = 3072 warps.
__global__ void __launch_bounds__(256) k_scan2(const float* __restrict__ A_logs)
{
    const int W = blockIdx.x*8 + (threadIdx.x >> 5);   // [0, 3072)
    const int lane = threadIdx.x & 31;
    const int cidx  = W >> 3;
    const int chunk = W & 7;
    const int bk = cidx / 24;
    const int e  = (cidx - bk*24)*8 + (lane >> 2);
    const int lj = lane & 3;
    const int k  = bk & 3;

    const float L2E = 1.4426950408889634f;
    float am[4]; bool okl = true;
    #pragma unroll
    for (int s = 0; s < 4; s++){
        int n = 4*s + lj;
        float av = -__expf(A_logs[(k*EE + e)*NNS + n]);
        am[s] = av * L2E;
        okl &= fabsf(av + (float)(n+1)) < 1e-4f * (float)(n+1);
    }
    const bool ok = __all_sync(0xffffffffu, okl);

    const int ch = bk*EE + e;
    const long chb = (long)ch*LL;
    const float* __restrict__ pd = g_delta + chb;
    const float* __restrict__ pu = g_du    + chb;
    const float* __restrict__ pb = g_B4 + (long)bk*LL*16;
    const float* __restrict__ pc = g_C4 + (long)bk*LL*16;
    float* __restrict__ py = g_y + chb;

    float4 h4 = *(const float4*)&g_hin[(ch*NCH + chunk)*16 + lj*4];
    float h0 = h4.x, h1 = h4.y, h2 = h4.z, h3 = h4.w;
    const int l0 = chunk*CHL;
    const float am0 = am[0];

    if (ok){
        for (int l = l0; l < l0 + CHL; l += 4){
            float4 d4 = *(const float4*)(pd + l);
            float4 u4 = *(const float4*)(pu + l);
            float dd[4] = {d4.x, d4.y, d4.z, d4.w};
            float uu[4] = {u4.x, u4.y, u4.z, u4.w};
            float ysv = 0.f;
            #pragma unroll
            for (int s = 0; s < 4; s++){
                float4 b4 = *(const float4*)(pb + (l+s)*16 + lj*4);
                float4 c4 = *(const float4*)(pc + (l+s)*16 + lj*4);
                float t  = ex2f(dd[s]*am0);
                float q4 = __shfl_sync(0xffffffffu, t, 3, 4);
                float dA1 = t*q4, dA2 = dA1*q4, dA3 = dA2*q4;
                float us = uu[s];
                h0 = fmaf(t,   h0, us*b4.x);
                h1 = fmaf(dA1, h1, us*b4.y);
                h2 = fmaf(dA2, h2, us*b4.z);
                h3 = fmaf(dA3, h3, us*b4.w);
                float p = h0*c4.x;
                p = fmaf(h1, c4.y, p);
                p = fmaf(h2, c4.z, p);
                p = fmaf(h3, c4.w, p);
                p += __shfl_xor_sync(0xffffffffu, p, 1);
                p += __shfl_xor_sync(0xffffffffu, p, 2);
                if (lj == s) ysv = p;
            }
            py[l + lj] = ysv;
        }
    } else {
        for (int l = l0; l < l0 + CHL; l += 4){
            float4 d4 = *(const float4*)(pd + l);
            float4 u4 = *(const float4*)(pu + l);
            float dd[4] = {d4.x, d4.y, d4.z, d4.w};
            float uu[4] = {u4.x, u4.y, u4.z, u4.w};
            float ysv = 0.f;
            #pragma unroll
            for (int s = 0; s < 4; s++){
                float4 b4 = *(const float4*)(pb + (l+s)*16 + lj*4);
                float4 c4 = *(const float4*)(pc + (l+s)*16 + lj*4);
                float us = uu[s];
                h0 = fmaf(ex2f(dd[s]*am[0]), h0, us*b4.x);
                h1 = fmaf(ex2f(dd[s]*am[1]), h1, us*b4.y);
                h2 = fmaf(ex2f(dd[s]*am[2]), h2, us*b4.z);
                h3 = fmaf(ex2f(dd[s]*am[3]), h3, us*b4.w);
                float p = h0*c4.x;
                p = fmaf(h1, c4.y, p);
                p = fmaf(h2, c4.z, p);
                p = fmaf(h3, c4.w, p);
                p += __shfl_xor_sync(0xffffffffu, p, 1);
                p += __shfl_xor_sync(0xffffffffu, p, 2);
                if (lj == s) ysv = p;
            }
            py[l + lj] = ysv;
        }
    }
}

// ------------------------- transpose WH directions into canonical -----------
__global__ void k_trans()
{
    __shared__ float s[32][33];
    const int zi = blockIdx.z;
    const int arr = zi & 1;
    const int e = (zi >> 1) % EE;
    const int b = zi / (EE*2);
    const int ti = blockIdx.x, tj = blockIdx.y;
    const int tx = threadIdx.x, ty = threadIdx.y;
    const int kdir = arr ? 3 : 1;
    const float* __restrict__ src = g_y + (long)((b*KK + kdir)*EE + e)*LL;
    float* __restrict__ dst = (arr ? g_yt3 : g_yt1) + (long)(b*EE + e)*LL;

    #pragma unroll
    for (int r = 0; r < 4; r++){
        int w = tj*32 + ty + r*8;
        int h = ti*32 + tx;
        float v;
        if (arr == 0) v = src[w*64 + h];
        else          v = src[(63 - w)*64 + (63 - h)];
        s[ty + r*8][tx] = v;
    }
    __syncthreads();
    #pragma unroll
    for (int r = 0; r < 4; r++){
        int h = ti*32 + ty + r*8;
        int w = tj*32 + tx;
        dst[h*64 + w] = s[tx][ty + r*8];
    }
}

// ------------------------- merge + D*xc + LayerNorm + gate ------------------
__global__ void __launch_bounds__(256) k_merge(const float* __restrict__ Ds, const float* __restrict__ gamma,
                        const float* __restrict__ beta)
{
    __shared__ float tb[32][193];
    __shared__ float sumD[EE];
    const int l0 = blockIdx.x * 32;
    const int b  = blockIdx.y;
    const int t  = threadIdx.x;

    if (t < EE) sumD[t] = Ds[t] + Ds[EE + t] + Ds[2*EE + t] + Ds[3*EE + t];

    const long y0b = (long)((b*KK + 0)*EE)*LL;
    const long y2b = (long)((b*KK + 2)*EE)*LL;
    const long ytb = (long)(b*EE)*LL;
    for (int idx = t; idx < EE*32; idx += 256){
        int e = idx >> 5, i = idx & 31;
        int l = l0 + i;
        float v = g_y[y0b + (long)e*LL + l]
                + g_y[y2b + (long)e*LL + (LL-1 - l)]
                + g_yt1[ytb + (long)e*LL + l]
                + g_yt3[ytb + (long)e*LL + l];
        tb[i][e] = v;
    }
    __syncthreads();
    for (int idx = t; idx < 32*EE; idx += 256){
        int i = idx / EE, e = idx - i*EE;
        tb[i][e] += sumD[e] * g_xc[(b*LL + l0 + i)*EE + e];
    }
    __syncthreads();

    const int li = t >> 3, ts = t & 7;
    float s1 = 0.f, s2 = 0.f;
    #pragma unroll
    for (int m = 0; m < 24; m++){
        float v = tb[li][ts + 8*m];
        s1 += v; s2 += v*v;
    }
    #pragma unroll
    for (int o = 1; o < 8; o <<= 1){
        s1 += __shfl_xor_sync(0xffffffffu, s1, o);
        s2 += __shfl_xor_sync(0xffffffffu, s2, o);
    }
    const float inv = 1.f / (float)EE;
    float mu = s1 * inv;
    float var = s2 * inv - mu*mu;
    float rstd = rsqrtf(var + 1e-5f);

    const long rowb = (long)(b*LL + l0 + li)*EE;
    #pragma unroll
    for (int m = 0; m < 24; m++){
        int e = ts + 8*m;
        float v = (tb[li][e] - mu) * rstd * gamma[e] + beta[e];
        g_ym[rowb + e] = v * g_z[rowb + e];
    }
}

// ------------------------- launcher -----------------------------------------
extern "C" void kernel_launch(void* const* d_in, const int* in_sizes, int n_in,
                              void* d_out, int out_size)
{
    const float* x    = (const float*)d_in[0];
    const float* ipw  = (const float*)d_in[1];
    const float* cw   = (const float*)d_in[2];
    const float* cb   = (const float*)d_in[3];
    const float* xpw  = (const float*)d_in[4];
    const float* dtw  = (const float*)d_in[5];
    const float* dtb  = (const float*)d_in[6];
    const float* alog = (const float*)d_in[7];
    const float* Ds   = (const float*)d_in[8];
    const float* lng  = (const float*)d_in[9];
    const float* lnb  = (const float*)d_in[10];
    const float* opw  = (const float*)d_in[11];
    float* out = (float*)d_out;

    k_gemm<DM, 1><<<dim3(128, 6), 256>>>(x, ipw, nullptr, 2*EE);
    k_conv<<<dim3(4, 64, BB), 256>>>(cw, cb);
    k_gemm<EE, 0><<<dim3(128, 3), 256>>>(nullptr, xpw, nullptr, C152);
    k_prep<<<BB*KK*128, 256>>>(dtw, dtb);
    k_scan1<<<336, 256>>>(alog);
    k_scanmid<<<192, 256>>>(alog);
    k_scan2<<<384, 256>>>(alog);
    k_trans<<<dim3(2, 2, BB*EE*2), dim3(32, 8)>>>();
    k_merge<<<dim3(128, BB), 256>>>(Ds, lng, lnb);
    k_gemm<EE, 2><<<dim3(128, 2), 256>>>(nullptr, opw, out, DM);
}